// round 3
// baseline (speedup 1.0000x reference)
#include <cuda_runtime.h>
#include <cstdint>

// GCN: out = GCNConv2( relu(GCNConv1(x)) )
// Factorization: per layer, Hs = dinv ⊙ (X W);  A[d] = Hs[d] + sum_{s->d} Hs[s];
//                out[d] = dinv[d]*A[d] + b   (relu after layer 1)

#define N_NODES 100000
#define N_EDGES 1600000
#define EMB 128
#define HID 128
#define RPR 64

// ---------------- scratch (device globals, allocation-free) ----------------
__device__ float g_dinv[N_NODES];
__device__ float g_Hs [(long long)N_NODES * HID];   // layer1 scaled hidden
__device__ float g_A  [(long long)N_NODES * HID];   // layer1 aggregation
__device__ float g_Hs2[(long long)N_NODES * RPR];   // layer2 scaled hidden
__device__ float g_A2 [(long long)N_NODES * RPR];   // layer2 aggregation

// ---------------- helpers ----------------
__device__ __forceinline__ unsigned long long ffma2(unsigned long long a,
                                                    unsigned long long b,
                                                    unsigned long long c) {
    unsigned long long d;
    asm("fma.rn.f32x2 %0, %1, %2, %3;" : "=l"(d) : "l"(a), "l"(b), "l"(c));
    return d;
}

__device__ __forceinline__ unsigned long long bcast2(float x) {
    unsigned long long r;
    unsigned int u = __float_as_uint(x);
    asm("mov.b64 %0, {%1, %1};" : "=l"(r) : "r"(u));
    return r;
}

__device__ __forceinline__ void unpack2(unsigned long long v, float& lo, float& hi) {
    unsigned int a, b;
    asm("mov.b64 {%0, %1}, %2;" : "=r"(a), "=r"(b) : "l"(v));
    lo = __uint_as_float(a);
    hi = __uint_as_float(b);
}

__device__ __forceinline__ void red_add_v4(float* p, float4 v) {
    asm volatile("red.global.add.v4.f32 [%0], {%1, %2, %3, %4};"
                 :: "l"(p), "f"(v.x), "f"(v.y), "f"(v.z), "f"(v.w) : "memory");
}

// ---------------- degree / dinv ----------------
__global__ void k_init_deg() {
    int i = blockIdx.x * blockDim.x + threadIdx.x;
    if (i < N_NODES) g_dinv[i] = 1.0f;   // self loop
}

__global__ void k_count_deg(const int* __restrict__ dst) {
    int stride = gridDim.x * blockDim.x;
    for (int e = blockIdx.x * blockDim.x + threadIdx.x; e < N_EDGES; e += stride)
        atomicAdd(&g_dinv[dst[e]], 1.0f);
}

__global__ void k_rsqrt_deg() {
    int i = blockIdx.x * blockDim.x + threadIdx.x;
    if (i < N_NODES) g_dinv[i] = rsqrtf(g_dinv[i]);
}

// ---------------- layer-1 GEMM: Hs = dinv * (x @ W1); A = Hs ----------------
// grid.y = 2 column tiles of 64 output cols (W tile 128x64 = 32KB smem).
__global__ __launch_bounds__(256, 2)
void k_gemm1(const float* __restrict__ x, const float* __restrict__ W1) {
    __shared__ unsigned long long Ws[128][32];  // [k][colpair], cols = 64*tile..
    const int colTile = blockIdx.y;

    for (int idx = threadIdx.x; idx < 128 * 32; idx += blockDim.x) {
        int k = idx >> 5, cp = idx & 31;
        float2 w = *(const float2*)&W1[k * HID + colTile * 64 + cp * 2];
        unsigned long long p;
        asm("mov.b64 %0, {%1, %2};" : "=l"(p)
            : "r"(__float_as_uint(w.x)), "r"(__float_as_uint(w.y)));
        Ws[k][cp] = p;
    }
    __syncthreads();

    const int row = blockIdx.x * blockDim.x + threadIdx.x;
    if (row >= N_NODES) return;

    unsigned long long acc[32];
#pragma unroll
    for (int c = 0; c < 32; c++) acc[c] = 0ull;

    const float4* xr = (const float4*)(x + (size_t)row * EMB);
    for (int kc = 0; kc < 8; kc++) {
        float4 v0 = __ldg(xr + kc * 4 + 0);
        float4 v1 = __ldg(xr + kc * 4 + 1);
        float4 v2 = __ldg(xr + kc * 4 + 2);
        float4 v3 = __ldg(xr + kc * 4 + 3);
        float xs[16] = {v0.x, v0.y, v0.z, v0.w, v1.x, v1.y, v1.z, v1.w,
                        v2.x, v2.y, v2.z, v2.w, v3.x, v3.y, v3.z, v3.w};
#pragma unroll
        for (int k = 0; k < 16; k++) {
            unsigned long long xk2 = bcast2(xs[k]);
            const unsigned long long* wr = Ws[kc * 16 + k];
#pragma unroll
            for (int c = 0; c < 32; c++) acc[c] = ffma2(xk2, wr[c], acc[c]);
        }
    }

    const float di = __ldg(&g_dinv[row]);
    float* hs = g_Hs + (size_t)row * HID + colTile * 64;
    float* aa = g_A  + (size_t)row * HID + colTile * 64;
#pragma unroll
    for (int q = 0; q < 16; q++) {
        float a0, a1, b0, b1;
        unpack2(acc[2 * q], a0, a1);
        unpack2(acc[2 * q + 1], b0, b1);
        float4 v = make_float4(a0 * di, a1 * di, b0 * di, b1 * di);
        *(float4*)(hs + q * 4) = v;
        *(float4*)(aa + q * 4) = v;
    }
}

// ---------------- layer-1 scatter: A[dst] += Hs[src] ----------------
// one warp per edge; 32 lanes x float4 = 128 floats
__global__ void k_scatter1(const int* __restrict__ src, const int* __restrict__ dst) {
    const int lane = threadIdx.x & 31;
    const int warp = (blockIdx.x * blockDim.x + threadIdx.x) >> 5;
    const int nwarps = (gridDim.x * blockDim.x) >> 5;
    for (int e = warp; e < N_EDGES; e += nwarps) {
        int s = __ldg(src + e);
        int d = __ldg(dst + e);
        float4 v = __ldg((const float4*)(g_Hs + (size_t)s * HID) + lane);
        red_add_v4(g_A + (size_t)d * HID + lane * 4, v);
    }
}

// ---------------- layer-2 GEMM (fused relu prologue) ----------------
// x1 = relu(dinv*A + b1);  Hs2 = dinv * (x1 @ W2);  A2 = Hs2
__global__ __launch_bounds__(256, 2)
void k_gemm2(const float* __restrict__ W2, const float* __restrict__ b1) {
    __shared__ unsigned long long Ws[128][32];  // 64 cols -> 32 pairs
    __shared__ float b1s[128];

    for (int idx = threadIdx.x; idx < 128 * 32; idx += blockDim.x) {
        int k = idx >> 5, cp = idx & 31;
        float2 w = *(const float2*)&W2[k * RPR + cp * 2];
        unsigned long long p;
        asm("mov.b64 %0, {%1, %2};" : "=l"(p)
            : "r"(__float_as_uint(w.x)), "r"(__float_as_uint(w.y)));
        Ws[k][cp] = p;
    }
    if (threadIdx.x < 128) b1s[threadIdx.x] = b1[threadIdx.x];
    __syncthreads();

    const int row = blockIdx.x * blockDim.x + threadIdx.x;
    if (row >= N_NODES) return;

    const float di = __ldg(&g_dinv[row]);
    unsigned long long acc[32];
#pragma unroll
    for (int c = 0; c < 32; c++) acc[c] = 0ull;

    const float4* ar = (const float4*)(g_A + (size_t)row * HID);
    for (int kc = 0; kc < 8; kc++) {
        float4 v0 = __ldg(ar + kc * 4 + 0);
        float4 v1 = __ldg(ar + kc * 4 + 1);
        float4 v2 = __ldg(ar + kc * 4 + 2);
        float4 v3 = __ldg(ar + kc * 4 + 3);
        float raw[16] = {v0.x, v0.y, v0.z, v0.w, v1.x, v1.y, v1.z, v1.w,
                         v2.x, v2.y, v2.z, v2.w, v3.x, v3.y, v3.z, v3.w};
#pragma unroll
        for (int k = 0; k < 16; k++) {
            float x1 = fmaxf(fmaf(di, raw[k], b1s[kc * 16 + k]), 0.0f);
            unsigned long long xk2 = bcast2(x1);
            const unsigned long long* wr = Ws[kc * 16 + k];
#pragma unroll
            for (int c = 0; c < 32; c++) acc[c] = ffma2(xk2, wr[c], acc[c]);
        }
    }

    float* hs = g_Hs2 + (size_t)row * RPR;
    float* aa = g_A2  + (size_t)row * RPR;
#pragma unroll
    for (int q = 0; q < 16; q++) {
        float a0, a1, b0, b1v;
        unpack2(acc[2 * q], a0, a1);
        unpack2(acc[2 * q + 1], b0, b1v);
        float4 v = make_float4(a0 * di, a1 * di, b0 * di, b1v * di);
        *(float4*)(hs + q * 4) = v;
        *(float4*)(aa + q * 4) = v;
    }
}

// ---------------- layer-2 scatter: A2[dst] += Hs2[src] ----------------
// half-warp (16 lanes x float4 = 64 floats) per edge
__global__ void k_scatter2(const int* __restrict__ src, const int* __restrict__ dst) {
    const int lane = threadIdx.x & 31;
    const int sub = lane >> 4;          // 0/1: which edge in the pair
    const int l16 = lane & 15;
    const int warp = (blockIdx.x * blockDim.x + threadIdx.x) >> 5;
    const int nwarps = (gridDim.x * blockDim.x) >> 5;
    for (int e = warp * 2 + sub; e < N_EDGES; e += nwarps * 2) {
        int s = __ldg(src + e);
        int d = __ldg(dst + e);
        float4 v = __ldg((const float4*)(g_Hs2 + (size_t)s * RPR) + l16);
        red_add_v4(g_A2 + (size_t)d * RPR + l16 * 4, v);
    }
}

// ---------------- epilogue: out = dinv*A2 + b2 ----------------
__global__ void k_finish(const float* __restrict__ b2, float* __restrict__ out) {
    int idx = blockIdx.x * blockDim.x + threadIdx.x;  // in float4 units
    if (idx >= N_NODES * (RPR / 4)) return;
    int i = idx >> 4;
    int c4 = (idx & 15) * 4;
    float di = g_dinv[i];
    float4 a = *(const float4*)(g_A2 + (size_t)i * RPR + c4);
    float4 b = __ldg((const float4*)(b2 + c4));
    float4 r = make_float4(fmaf(di, a.x, b.x), fmaf(di, a.y, b.y),
                           fmaf(di, a.z, b.z), fmaf(di, a.w, b.w));
    *(float4*)(out + (size_t)i * RPR + c4) = r;
}

// ---------------- launch ----------------
extern "C" void kernel_launch(void* const* d_in, const int* in_sizes, int n_in,
                              void* d_out, int out_size) {
    const int*   edge = (const int*)d_in[0];     // [2, E]: src row, dst row
    const float* x    = (const float*)d_in[1];   // [N, 128]
    const float* W1   = (const float*)d_in[2];   // [128, 128]
    const float* b1   = (const float*)d_in[3];   // [128]
    const float* W2   = (const float*)d_in[4];   // [128, 64]
    const float* b2   = (const float*)d_in[5];   // [64]
    float* out = (float*)d_out;                  // [N, 64]

    const int* src = edge;
    const int* dst = edge + N_EDGES;

    k_init_deg<<<(N_NODES + 255) / 256, 256>>>();
    k_count_deg<<<2048, 256>>>(dst);
    k_rsqrt_deg<<<(N_NODES + 255) / 256, 256>>>();

    {
        dim3 grid((N_NODES + 255) / 256, 2);
        k_gemm1<<<grid, 256>>>(x, W1);
    }
    k_scatter1<<<2368, 256>>>(src, dst);
    k_gemm2<<<(N_NODES + 255) / 256, 256>>>(W2, b1);
    k_scatter2<<<2368, 256>>>(src, dst);
    k_finish<<<(N_NODES * (RPR / 4) + 255) / 256, 256>>>(b2, out);
}

// round 4
// speedup vs baseline: 1.3052x; 1.3052x over previous
#include <cuda_runtime.h>
#include <cstdint>

// GCN: out = GCNConv2( relu(GCNConv1(x)) )
// Per layer: Hs = dinv ⊙ (X W);  agg[d] = Hs[d] + sum_{s->d} Hs[s] (CSR gather);
//            layer1: x1 = relu(dinv*agg + b1);  layer2: out = dinv*agg + b2

#define N_NODES 100000
#define N_EDGES 1600000
#define EMB 128
#define HID 128
#define RPR 64
#define SCAN_BLOCKS 391   // ceil(100000/256)

// ---------------- scratch (device globals, allocation-free) ----------------
__device__ float g_dinv[N_NODES];
__device__ float g_Hs [(long long)N_NODES * HID];   // layer1 scaled hidden
__device__ float g_X1 [(long long)N_NODES * HID];   // relu(conv1) output
__device__ float g_Hs2[(long long)N_NODES * RPR];   // layer2 scaled hidden
__device__ int   g_cnt[N_NODES];
__device__ int   g_rowptr[N_NODES + 1];
__device__ int   g_cur[N_NODES];
__device__ int   g_blocksum[SCAN_BLOCKS];
__device__ int   g_adj[N_EDGES];

// ---------------- helpers ----------------
__device__ __forceinline__ unsigned long long ffma2(unsigned long long a,
                                                    unsigned long long b,
                                                    unsigned long long c) {
    unsigned long long d;
    asm("fma.rn.f32x2 %0, %1, %2, %3;" : "=l"(d) : "l"(a), "l"(b), "l"(c));
    return d;
}

__device__ __forceinline__ unsigned long long bcast2(float x) {
    unsigned long long r;
    unsigned int u = __float_as_uint(x);
    asm("mov.b64 %0, {%1, %1};" : "=l"(r) : "r"(u));
    return r;
}

__device__ __forceinline__ unsigned long long pack2(float a, float b) {
    unsigned long long r;
    asm("mov.b64 %0, {%1, %2};" : "=l"(r)
        : "r"(__float_as_uint(a)), "r"(__float_as_uint(b)));
    return r;
}

__device__ __forceinline__ void unpack2(unsigned long long v, float& lo, float& hi) {
    unsigned int a, b;
    asm("mov.b64 {%0, %1}, %2;" : "=r"(a), "=r"(b) : "l"(v));
    lo = __uint_as_float(a);
    hi = __uint_as_float(b);
}

// ---------------- CSR build + degree ----------------
__global__ void k_zero() {
    int i = blockIdx.x * blockDim.x + threadIdx.x;
    if (i < N_NODES) g_cnt[i] = 0;
}

__global__ void k_hist(const int* __restrict__ dst) {
    int stride = gridDim.x * blockDim.x;
    for (int e = blockIdx.x * blockDim.x + threadIdx.x; e < N_EDGES; e += stride)
        atomicAdd(&g_cnt[dst[e]], 1);
}

__global__ void k_breduce() {
    __shared__ int sh[256];
    int i = blockIdx.x * 256 + threadIdx.x;
    int v = (i < N_NODES) ? g_cnt[i] : 0;
    sh[threadIdx.x] = v;
    __syncthreads();
    for (int s = 128; s > 0; s >>= 1) {
        if (threadIdx.x < s) sh[threadIdx.x] += sh[threadIdx.x + s];
        __syncthreads();
    }
    if (threadIdx.x == 0) g_blocksum[blockIdx.x] = sh[0];
}

__global__ void k_scanb() {   // single block of 512, exclusive scan of block sums
    __shared__ int sh[512];
    int t = threadIdx.x;
    int v = (t < SCAN_BLOCKS) ? g_blocksum[t] : 0;
    sh[t] = v;
    __syncthreads();
    for (int off = 1; off < 512; off <<= 1) {
        int add = 0;
        if (t >= off) add = sh[t - off];
        __syncthreads();
        sh[t] += add;
        __syncthreads();
    }
    if (t < SCAN_BLOCKS) g_blocksum[t] = sh[t] - v;   // exclusive
}

__global__ void k_scanfinal() {
    __shared__ int sh[256];
    int t = threadIdx.x;
    int i = blockIdx.x * 256 + t;
    int v = (i < N_NODES) ? g_cnt[i] : 0;
    sh[t] = v;
    __syncthreads();
    for (int off = 1; off < 256; off <<= 1) {
        int add = 0;
        if (t >= off) add = sh[t - off];
        __syncthreads();
        sh[t] += add;
        __syncthreads();
    }
    int excl = sh[t] - v + g_blocksum[blockIdx.x];
    if (i < N_NODES) {
        g_rowptr[i] = excl;
        g_cur[i]    = excl;
        g_dinv[i]   = rsqrtf(1.0f + (float)v);   // +1 for self loop
    }
    if (i == N_NODES - 1) g_rowptr[N_NODES] = excl + v;
}

__global__ void k_fill(const int* __restrict__ src, const int* __restrict__ dst) {
    int stride = gridDim.x * blockDim.x;
    for (int e = blockIdx.x * blockDim.x + threadIdx.x; e < N_EDGES; e += stride) {
        int d = dst[e];
        int pos = atomicAdd(&g_cur[d], 1);
        g_adj[pos] = src[e];
    }
}

// ---------------- layer-1 GEMM: Hs = dinv * (x @ W1) ----------------
// 4 rows/thread register blocking; full 128 cols per block; k in 2 smem passes.
// warp w = colgroup (16 cols); lane l -> rows base + l + 32j, j=0..3.
__global__ __launch_bounds__(256, 2)
void k_gemm1(const float* __restrict__ x, const float* __restrict__ W1) {
    __shared__ unsigned long long Ws[64][64];   // 32KB: 64 k-rows x 128 cols (as pairs)
    const int lane = threadIdx.x & 31;
    const int warp = threadIdx.x >> 5;          // colgroup 0..7 -> cols [warp*16, +16)
    const int rowBase = blockIdx.x * 128 + lane;

    unsigned long long acc[4][8];
#pragma unroll
    for (int j = 0; j < 4; j++)
#pragma unroll
        for (int c = 0; c < 8; c++) acc[j][c] = 0ull;

    bool valid[4];
    const float4* xr[4];
#pragma unroll
    for (int j = 0; j < 4; j++) {
        int r = rowBase + 32 * j;
        valid[j] = (r < N_NODES);
        xr[j] = (const float4*)(x + (size_t)(valid[j] ? r : 0) * EMB);
    }

    for (int p = 0; p < 2; p++) {
        __syncthreads();
        for (int idx = threadIdx.x; idx < 64 * 64; idx += 256) {
            int k = idx >> 6, cp = idx & 63;
            float2 w = *(const float2*)&W1[(p * 64 + k) * HID + cp * 2];
            Ws[k][cp] = pack2(w.x, w.y);
        }
        __syncthreads();

#pragma unroll
        for (int kc = 0; kc < 16; kc++) {
            float4 xv[4];
#pragma unroll
            for (int j = 0; j < 4; j++) xv[j] = __ldg(xr[j] + p * 16 + kc);
#pragma unroll
            for (int kk = 0; kk < 4; kk++) {
                int k = kc * 4 + kk;
                const unsigned long long* wr = &Ws[k][warp * 8];
                unsigned long long xb[4];
#pragma unroll
                for (int j = 0; j < 4; j++)
                    xb[j] = bcast2(((const float*)&xv[j])[kk]);
#pragma unroll
                for (int c = 0; c < 8; c++) {
                    unsigned long long w = wr[c];
                    acc[0][c] = ffma2(xb[0], w, acc[0][c]);
                    acc[1][c] = ffma2(xb[1], w, acc[1][c]);
                    acc[2][c] = ffma2(xb[2], w, acc[2][c]);
                    acc[3][c] = ffma2(xb[3], w, acc[3][c]);
                }
            }
        }
    }

#pragma unroll
    for (int j = 0; j < 4; j++) {
        if (!valid[j]) continue;
        int r = rowBase + 32 * j;
        float di = __ldg(&g_dinv[r]);
        float* hs = g_Hs + (size_t)r * HID + warp * 16;
#pragma unroll
        for (int q = 0; q < 4; q++) {
            float a0, a1, b0, b1;
            unpack2(acc[j][2 * q],     a0, a1);
            unpack2(acc[j][2 * q + 1], b0, b1);
            *(float4*)(hs + q * 4) =
                make_float4(a0 * di, a1 * di, b0 * di, b1 * di);
        }
    }
}

// ---------------- layer-1 aggregate + relu + bias: x1 = relu(dinv*(Hs[d]+sum)+b1)
__global__ void k_agg1(const float* __restrict__ b1) {
    int gw = (blockIdx.x * blockDim.x + threadIdx.x) >> 5;
    if (gw >= N_NODES) return;
    const int lane = threadIdx.x & 31;
    const float4* hs = (const float4*)g_Hs;

    float4 acc = __ldg(hs + (size_t)gw * 32 + lane);   // self loop
    int beg = g_rowptr[gw], end = g_rowptr[gw + 1];
    int i = beg;
    for (; i + 4 <= end; i += 4) {
        int s0 = __ldg(g_adj + i),     s1 = __ldg(g_adj + i + 1);
        int s2 = __ldg(g_adj + i + 2), s3 = __ldg(g_adj + i + 3);
        float4 v0 = __ldg(hs + (size_t)s0 * 32 + lane);
        float4 v1 = __ldg(hs + (size_t)s1 * 32 + lane);
        float4 v2 = __ldg(hs + (size_t)s2 * 32 + lane);
        float4 v3 = __ldg(hs + (size_t)s3 * 32 + lane);
        acc.x += (v0.x + v1.x) + (v2.x + v3.x);
        acc.y += (v0.y + v1.y) + (v2.y + v3.y);
        acc.z += (v0.z + v1.z) + (v2.z + v3.z);
        acc.w += (v0.w + v1.w) + (v2.w + v3.w);
    }
    for (; i < end; i++) {
        int s = __ldg(g_adj + i);
        float4 v = __ldg(hs + (size_t)s * 32 + lane);
        acc.x += v.x; acc.y += v.y; acc.z += v.z; acc.w += v.w;
    }
    float di = __ldg(&g_dinv[gw]);
    float4 b = __ldg((const float4*)b1 + lane);
    float4 r = make_float4(fmaxf(fmaf(di, acc.x, b.x), 0.0f),
                           fmaxf(fmaf(di, acc.y, b.y), 0.0f),
                           fmaxf(fmaf(di, acc.z, b.z), 0.0f),
                           fmaxf(fmaf(di, acc.w, b.w), 0.0f));
    ((float4*)g_X1)[(size_t)gw * 32 + lane] = r;
}

// ---------------- layer-2 GEMM: Hs2 = dinv * (x1 @ W2) ----------------
// block = 256 rows x 64 cols; warp: cg = warp&3 (16 cols), rh = warp>>2.
__global__ __launch_bounds__(256, 2)
void k_gemm2(const float* __restrict__ W2) {
    __shared__ unsigned long long Ws[128][32];   // 32KB: 128 k x 64 cols as pairs
    const int lane = threadIdx.x & 31;
    const int warp = threadIdx.x >> 5;
    const int cg = warp & 3;                     // cols [cg*16, +16)
    const int rh = warp >> 2;
    const int rowBase = blockIdx.x * 256 + rh * 128 + lane;

    for (int idx = threadIdx.x; idx < 128 * 32; idx += 256) {
        int k = idx >> 5, cp = idx & 31;
        float2 w = *(const float2*)&W2[k * RPR + cp * 2];
        Ws[k][cp] = pack2(w.x, w.y);
    }
    __syncthreads();

    unsigned long long acc[4][8];
#pragma unroll
    for (int j = 0; j < 4; j++)
#pragma unroll
        for (int c = 0; c < 8; c++) acc[j][c] = 0ull;

    bool valid[4];
    const float4* xr[4];
#pragma unroll
    for (int j = 0; j < 4; j++) {
        int r = rowBase + 32 * j;
        valid[j] = (r < N_NODES);
        xr[j] = (const float4*)(g_X1 + (size_t)(valid[j] ? r : 0) * HID);
    }

#pragma unroll 4
    for (int kc = 0; kc < 32; kc++) {
        float4 xv[4];
#pragma unroll
        for (int j = 0; j < 4; j++) xv[j] = __ldg(xr[j] + kc);
#pragma unroll
        for (int kk = 0; kk < 4; kk++) {
            int k = kc * 4 + kk;
            const unsigned long long* wr = &Ws[k][cg * 8];
            unsigned long long xb[4];
#pragma unroll
            for (int j = 0; j < 4; j++)
                xb[j] = bcast2(((const float*)&xv[j])[kk]);
#pragma unroll
            for (int c = 0; c < 8; c++) {
                unsigned long long w = wr[c];
                acc[0][c] = ffma2(xb[0], w, acc[0][c]);
                acc[1][c] = ffma2(xb[1], w, acc[1][c]);
                acc[2][c] = ffma2(xb[2], w, acc[2][c]);
                acc[3][c] = ffma2(xb[3], w, acc[3][c]);
            }
        }
    }

#pragma unroll
    for (int j = 0; j < 4; j++) {
        if (!valid[j]) continue;
        int r = rowBase + 32 * j;
        float di = __ldg(&g_dinv[r]);
        float* hs = g_Hs2 + (size_t)r * RPR + cg * 16;
#pragma unroll
        for (int q = 0; q < 4; q++) {
            float a0, a1, b0, b1;
            unpack2(acc[j][2 * q],     a0, a1);
            unpack2(acc[j][2 * q + 1], b0, b1);
            *(float4*)(hs + q * 4) =
                make_float4(a0 * di, a1 * di, b0 * di, b1 * di);
        }
    }
}

// ---------------- layer-2 aggregate + bias -> out ----------------
// half-warp (16 lanes x float4 = 64 floats) per node
__global__ void k_agg2(const float* __restrict__ b2, float* __restrict__ out) {
    int gh = (blockIdx.x * blockDim.x + threadIdx.x) >> 4;
    if (gh >= N_NODES) return;
    const int l = threadIdx.x & 15;
    const float4* hs = (const float4*)g_Hs2;

    float4 acc = __ldg(hs + (size_t)gh * 16 + l);   // self loop
    int beg = g_rowptr[gh], end = g_rowptr[gh + 1];
    int i = beg;
    for (; i + 4 <= end; i += 4) {
        int s0 = __ldg(g_adj + i),     s1 = __ldg(g_adj + i + 1);
        int s2 = __ldg(g_adj + i + 2), s3 = __ldg(g_adj + i + 3);
        float4 v0 = __ldg(hs + (size_t)s0 * 16 + l);
        float4 v1 = __ldg(hs + (size_t)s1 * 16 + l);
        float4 v2 = __ldg(hs + (size_t)s2 * 16 + l);
        float4 v3 = __ldg(hs + (size_t)s3 * 16 + l);
        acc.x += (v0.x + v1.x) + (v2.x + v3.x);
        acc.y += (v0.y + v1.y) + (v2.y + v3.y);
        acc.z += (v0.z + v1.z) + (v2.z + v3.z);
        acc.w += (v0.w + v1.w) + (v2.w + v3.w);
    }
    for (; i < end; i++) {
        int s = __ldg(g_adj + i);
        float4 v = __ldg(hs + (size_t)s * 16 + l);
        acc.x += v.x; acc.y += v.y; acc.z += v.z; acc.w += v.w;
    }
    float di = __ldg(&g_dinv[gh]);
    float4 b = __ldg((const float4*)b2 + l);
    ((float4*)out)[(size_t)gh * 16 + l] =
        make_float4(fmaf(di, acc.x, b.x), fmaf(di, acc.y, b.y),
                    fmaf(di, acc.z, b.z), fmaf(di, acc.w, b.w));
}

// ---------------- launch ----------------
extern "C" void kernel_launch(void* const* d_in, const int* in_sizes, int n_in,
                              void* d_out, int out_size) {
    const int*   edge = (const int*)d_in[0];     // [2, E]: src row, dst row
    const float* x    = (const float*)d_in[1];   // [N, 128]
    const float* W1   = (const float*)d_in[2];   // [128, 128]
    const float* b1   = (const float*)d_in[3];   // [128]
    const float* W2   = (const float*)d_in[4];   // [128, 64]
    const float* b2   = (const float*)d_in[5];   // [64]
    float* out = (float*)d_out;                  // [N, 64]

    const int* src = edge;
    const int* dst = edge + N_EDGES;

    // CSR build (+ degree/dinv)
    k_zero<<<SCAN_BLOCKS, 256>>>();
    k_hist<<<2048, 256>>>(dst);
    k_breduce<<<SCAN_BLOCKS, 256>>>();
    k_scanb<<<1, 512>>>();
    k_scanfinal<<<SCAN_BLOCKS, 256>>>();
    k_fill<<<2048, 256>>>(src, dst);

    // layer 1
    k_gemm1<<<(N_NODES + 127) / 128, 256>>>(x, W1);
    k_agg1<<<(N_NODES * 32 + 255) / 256, 256>>>(b1);

    // layer 2
    k_gemm2<<<(N_NODES + 255) / 256, 256>>>(W2);
    k_agg2<<<(N_NODES * 16 + 255) / 256, 256>>>(b2, out);
}

// round 5
// speedup vs baseline: 1.4671x; 1.1241x over previous
#include <cuda_runtime.h>
#include <cuda_fp16.h>
#include <cstdint>

// GCN: out = GCNConv2( relu(GCNConv1(x)) )
// Per layer: Hs = dinv ⊙ (X W)  (stored fp16);  agg[d] = Hs[d] + sum_{s->d} Hs[s] (CSR gather);
//            layer1: x1 = relu(dinv*agg + b1);  layer2: out = dinv*agg + b2

#define N_NODES 100000
#define N_EDGES 1600000
#define EMB 128
#define HID 128
#define RPR 64
#define SCAN_BLOCKS 391   // ceil(100000/256)

// ---------------- scratch (device globals, allocation-free) ----------------
__device__ float  g_dinv[N_NODES];
__device__ __half g_Hs [(long long)N_NODES * HID];   // layer1 scaled hidden (fp16 messages)
__device__ float  g_X1 [(long long)N_NODES * HID];   // relu(conv1) output (fp32)
__device__ __half g_Hs2[(long long)N_NODES * RPR];   // layer2 scaled hidden (fp16 messages)
__device__ int    g_cnt[N_NODES];
__device__ int    g_rowptr[N_NODES + 1];
__device__ int    g_cur[N_NODES];
__device__ int    g_blocksum[SCAN_BLOCKS];
__device__ int    g_adj[N_EDGES];

// ---------------- helpers ----------------
__device__ __forceinline__ unsigned long long ffma2(unsigned long long a,
                                                    unsigned long long b,
                                                    unsigned long long c) {
    unsigned long long d;
    asm("fma.rn.f32x2 %0, %1, %2, %3;" : "=l"(d) : "l"(a), "l"(b), "l"(c));
    return d;
}

__device__ __forceinline__ unsigned long long bcast2(float x) {
    unsigned long long r;
    unsigned int u = __float_as_uint(x);
    asm("mov.b64 %0, {%1, %1};" : "=l"(r) : "r"(u));
    return r;
}

__device__ __forceinline__ unsigned long long pack2(float a, float b) {
    unsigned long long r;
    asm("mov.b64 %0, {%1, %2};" : "=l"(r)
        : "r"(__float_as_uint(a)), "r"(__float_as_uint(b)));
    return r;
}

__device__ __forceinline__ void unpack2(unsigned long long v, float& lo, float& hi) {
    unsigned int a, b;
    asm("mov.b64 {%0, %1}, %2;" : "=r"(a), "=r"(b) : "l"(v));
    lo = __uint_as_float(a);
    hi = __uint_as_float(b);
}

__device__ __forceinline__ unsigned int h2u(float a, float b) {
    __half2 h = __floats2half2_rn(a, b);
    return *reinterpret_cast<unsigned int*>(&h);
}

__device__ __forceinline__ float2 u2f(unsigned int u) {
    __half2 h = *reinterpret_cast<__half2*>(&u);
    return __half22float2(h);
}

// ---------------- CSR build + degree ----------------
__global__ void k_zero() {
    int i = blockIdx.x * blockDim.x + threadIdx.x;
    if (i < N_NODES) g_cnt[i] = 0;
}

__global__ void k_hist(const int* __restrict__ dst) {
    int stride = gridDim.x * blockDim.x;
    for (int e = blockIdx.x * blockDim.x + threadIdx.x; e < N_EDGES; e += stride)
        atomicAdd(&g_cnt[dst[e]], 1);
}

__global__ void k_breduce() {
    __shared__ int sh[256];
    int i = blockIdx.x * 256 + threadIdx.x;
    int v = (i < N_NODES) ? g_cnt[i] : 0;
    sh[threadIdx.x] = v;
    __syncthreads();
    for (int s = 128; s > 0; s >>= 1) {
        if (threadIdx.x < s) sh[threadIdx.x] += sh[threadIdx.x + s];
        __syncthreads();
    }
    if (threadIdx.x == 0) g_blocksum[blockIdx.x] = sh[0];
}

__global__ void k_scanb() {   // single block of 512, exclusive scan of block sums
    __shared__ int sh[512];
    int t = threadIdx.x;
    int v = (t < SCAN_BLOCKS) ? g_blocksum[t] : 0;
    sh[t] = v;
    __syncthreads();
    for (int off = 1; off < 512; off <<= 1) {
        int add = 0;
        if (t >= off) add = sh[t - off];
        __syncthreads();
        sh[t] += add;
        __syncthreads();
    }
    if (t < SCAN_BLOCKS) g_blocksum[t] = sh[t] - v;   // exclusive
}

__global__ void k_scanfinal() {
    __shared__ int sh[256];
    int t = threadIdx.x;
    int i = blockIdx.x * 256 + t;
    int v = (i < N_NODES) ? g_cnt[i] : 0;
    sh[t] = v;
    __syncthreads();
    for (int off = 1; off < 256; off <<= 1) {
        int add = 0;
        if (t >= off) add = sh[t - off];
        __syncthreads();
        sh[t] += add;
        __syncthreads();
    }
    int excl = sh[t] - v + g_blocksum[blockIdx.x];
    if (i < N_NODES) {
        g_rowptr[i] = excl;
        g_cur[i]    = excl;
        g_dinv[i]   = rsqrtf(1.0f + (float)v);   // +1 for self loop
    }
    if (i == N_NODES - 1) g_rowptr[N_NODES] = excl + v;
}

__global__ void k_fill(const int* __restrict__ src, const int* __restrict__ dst) {
    int stride = gridDim.x * blockDim.x;
    for (int e = blockIdx.x * blockDim.x + threadIdx.x; e < N_EDGES; e += stride) {
        int d = dst[e];
        int pos = atomicAdd(&g_cur[d], 1);
        g_adj[pos] = src[e];
    }
}

// ---------------- layer-1 GEMM: Hs = dinv * (x @ W1)  (fp16 out) ----------------
// 4 rows/thread register blocking; full 128 cols per block; k in 2 smem passes.
// warp w = colgroup (16 cols); lane l -> rows base + l + 32j, j=0..3.
__global__ __launch_bounds__(256, 2)
void k_gemm1(const float* __restrict__ x, const float* __restrict__ W1) {
    __shared__ unsigned long long Ws[64][64];   // 32KB: 64 k-rows x 128 cols (as pairs)
    const int lane = threadIdx.x & 31;
    const int warp = threadIdx.x >> 5;          // colgroup 0..7 -> cols [warp*16, +16)
    const int rowBase = blockIdx.x * 128 + lane;

    unsigned long long acc[4][8];
#pragma unroll
    for (int j = 0; j < 4; j++)
#pragma unroll
        for (int c = 0; c < 8; c++) acc[j][c] = 0ull;

    bool valid[4];
    const float4* xr[4];
#pragma unroll
    for (int j = 0; j < 4; j++) {
        int r = rowBase + 32 * j;
        valid[j] = (r < N_NODES);
        xr[j] = (const float4*)(x + (size_t)(valid[j] ? r : 0) * EMB);
    }

    for (int p = 0; p < 2; p++) {
        __syncthreads();
        for (int idx = threadIdx.x; idx < 64 * 64; idx += 256) {
            int k = idx >> 6, cp = idx & 63;
            float2 w = *(const float2*)&W1[(p * 64 + k) * HID + cp * 2];
            Ws[k][cp] = pack2(w.x, w.y);
        }
        __syncthreads();

#pragma unroll
        for (int kc = 0; kc < 16; kc++) {
            float4 xv[4];
#pragma unroll
            for (int j = 0; j < 4; j++) xv[j] = __ldg(xr[j] + p * 16 + kc);
#pragma unroll
            for (int kk = 0; kk < 4; kk++) {
                int k = kc * 4 + kk;
                const unsigned long long* wr = &Ws[k][warp * 8];
                unsigned long long xb[4];
#pragma unroll
                for (int j = 0; j < 4; j++)
                    xb[j] = bcast2(((const float*)&xv[j])[kk]);
#pragma unroll
                for (int c = 0; c < 8; c++) {
                    unsigned long long w = wr[c];
                    acc[0][c] = ffma2(xb[0], w, acc[0][c]);
                    acc[1][c] = ffma2(xb[1], w, acc[1][c]);
                    acc[2][c] = ffma2(xb[2], w, acc[2][c]);
                    acc[3][c] = ffma2(xb[3], w, acc[3][c]);
                }
            }
        }
    }

#pragma unroll
    for (int j = 0; j < 4; j++) {
        if (!valid[j]) continue;
        int r = rowBase + 32 * j;
        float di = __ldg(&g_dinv[r]);
        unsigned int h[8];
#pragma unroll
        for (int q = 0; q < 8; q++) {
            float a0, a1;
            unpack2(acc[j][q], a0, a1);
            h[q] = h2u(a0 * di, a1 * di);
        }
        __half* hp = g_Hs + (size_t)r * HID + warp * 16;
        *(uint4*)(hp)     = make_uint4(h[0], h[1], h[2], h[3]);
        *(uint4*)(hp + 8) = make_uint4(h[4], h[5], h[6], h[7]);
    }
}

// ---------------- layer-1 aggregate + relu + bias: x1 = relu(dinv*(Hs[d]+sum)+b1)
// warp per node; lane covers 4 consecutive cols (uint2 = 4 halfs)
__global__ void k_agg1(const float* __restrict__ b1) {
    int gw = (blockIdx.x * blockDim.x + threadIdx.x) >> 5;
    if (gw >= N_NODES) return;
    const int lane = threadIdx.x & 31;
    const uint2* hs = (const uint2*)g_Hs;     // row stride = 32 uint2

    uint2 sv = __ldg(hs + (size_t)gw * 32 + lane);   // self loop
    float2 f0 = u2f(sv.x), f1 = u2f(sv.y);
    float4 acc = make_float4(f0.x, f0.y, f1.x, f1.y);

    int beg = g_rowptr[gw], end = g_rowptr[gw + 1];
    int i = beg;
    for (; i + 4 <= end; i += 4) {
        int s0 = __ldg(g_adj + i),     s1 = __ldg(g_adj + i + 1);
        int s2 = __ldg(g_adj + i + 2), s3 = __ldg(g_adj + i + 3);
        uint2 v0 = __ldg(hs + (size_t)s0 * 32 + lane);
        uint2 v1 = __ldg(hs + (size_t)s1 * 32 + lane);
        uint2 v2 = __ldg(hs + (size_t)s2 * 32 + lane);
        uint2 v3 = __ldg(hs + (size_t)s3 * 32 + lane);
        float2 a0 = u2f(v0.x), a1 = u2f(v0.y);
        float2 b0 = u2f(v1.x), b1v = u2f(v1.y);
        float2 c0 = u2f(v2.x), c1 = u2f(v2.y);
        float2 d0 = u2f(v3.x), d1 = u2f(v3.y);
        acc.x += (a0.x + b0.x) + (c0.x + d0.x);
        acc.y += (a0.y + b0.y) + (c0.y + d0.y);
        acc.z += (a1.x + b1v.x) + (c1.x + d1.x);
        acc.w += (a1.y + b1v.y) + (c1.y + d1.y);
    }
    for (; i < end; i++) {
        int s = __ldg(g_adj + i);
        uint2 v = __ldg(hs + (size_t)s * 32 + lane);
        float2 a0 = u2f(v.x), a1 = u2f(v.y);
        acc.x += a0.x; acc.y += a0.y; acc.z += a1.x; acc.w += a1.y;
    }
    float di = __ldg(&g_dinv[gw]);
    float4 b = __ldg((const float4*)b1 + lane);
    float4 r = make_float4(fmaxf(fmaf(di, acc.x, b.x), 0.0f),
                           fmaxf(fmaf(di, acc.y, b.y), 0.0f),
                           fmaxf(fmaf(di, acc.z, b.z), 0.0f),
                           fmaxf(fmaf(di, acc.w, b.w), 0.0f));
    ((float4*)g_X1)[(size_t)gw * 32 + lane] = r;
}

// ---------------- layer-2 GEMM: Hs2 = dinv * (x1 @ W2)  (fp16 out) ----------------
// block = 256 rows x 64 cols; warp: cg = warp&3 (16 cols), rh = warp>>2.
__global__ __launch_bounds__(256, 2)
void k_gemm2(const float* __restrict__ W2) {
    __shared__ unsigned long long Ws[128][32];   // 32KB: 128 k x 64 cols as pairs
    const int lane = threadIdx.x & 31;
    const int warp = threadIdx.x >> 5;
    const int cg = warp & 3;                     // cols [cg*16, +16)
    const int rh = warp >> 2;
    const int rowBase = blockIdx.x * 256 + rh * 128 + lane;

    for (int idx = threadIdx.x; idx < 128 * 32; idx += 256) {
        int k = idx >> 5, cp = idx & 31;
        float2 w = *(const float2*)&W2[k * RPR + cp * 2];
        Ws[k][cp] = pack2(w.x, w.y);
    }
    __syncthreads();

    unsigned long long acc[4][8];
#pragma unroll
    for (int j = 0; j < 4; j++)
#pragma unroll
        for (int c = 0; c < 8; c++) acc[j][c] = 0ull;

    bool valid[4];
    const float4* xr[4];
#pragma unroll
    for (int j = 0; j < 4; j++) {
        int r = rowBase + 32 * j;
        valid[j] = (r < N_NODES);
        xr[j] = (const float4*)(g_X1 + (size_t)(valid[j] ? r : 0) * HID);
    }

#pragma unroll 4
    for (int kc = 0; kc < 32; kc++) {
        float4 xv[4];
#pragma unroll
        for (int j = 0; j < 4; j++) xv[j] = __ldg(xr[j] + kc);
#pragma unroll
        for (int kk = 0; kk < 4; kk++) {
            int k = kc * 4 + kk;
            const unsigned long long* wr = &Ws[k][cg * 8];
            unsigned long long xb[4];
#pragma unroll
            for (int j = 0; j < 4; j++)
                xb[j] = bcast2(((const float*)&xv[j])[kk]);
#pragma unroll
            for (int c = 0; c < 8; c++) {
                unsigned long long w = wr[c];
                acc[0][c] = ffma2(xb[0], w, acc[0][c]);
                acc[1][c] = ffma2(xb[1], w, acc[1][c]);
                acc[2][c] = ffma2(xb[2], w, acc[2][c]);
                acc[3][c] = ffma2(xb[3], w, acc[3][c]);
            }
        }
    }

#pragma unroll
    for (int j = 0; j < 4; j++) {
        if (!valid[j]) continue;
        int r = rowBase + 32 * j;
        float di = __ldg(&g_dinv[r]);
        unsigned int h[8];
#pragma unroll
        for (int q = 0; q < 8; q++) {
            float a0, a1;
            unpack2(acc[j][q], a0, a1);
            h[q] = h2u(a0 * di, a1 * di);
        }
        __half* hp = g_Hs2 + (size_t)r * RPR + cg * 16;
        *(uint4*)(hp)     = make_uint4(h[0], h[1], h[2], h[3]);
        *(uint4*)(hp + 8) = make_uint4(h[4], h[5], h[6], h[7]);
    }
}

// ---------------- layer-2 aggregate + bias -> out ----------------
// half-warp (16 lanes x uint2 = 64 halfs) per node
__global__ void k_agg2(const float* __restrict__ b2, float* __restrict__ out) {
    int gh = (blockIdx.x * blockDim.x + threadIdx.x) >> 4;
    if (gh >= N_NODES) return;
    const int l = threadIdx.x & 15;
    const uint2* hs = (const uint2*)g_Hs2;    // row stride = 16 uint2

    uint2 sv = __ldg(hs + (size_t)gh * 16 + l);   // self loop
    float2 f0 = u2f(sv.x), f1 = u2f(sv.y);
    float4 acc = make_float4(f0.x, f0.y, f1.x, f1.y);

    int beg = g_rowptr[gh], end = g_rowptr[gh + 1];
    int i = beg;
    for (; i + 4 <= end; i += 4) {
        int s0 = __ldg(g_adj + i),     s1 = __ldg(g_adj + i + 1);
        int s2 = __ldg(g_adj + i + 2), s3 = __ldg(g_adj + i + 3);
        uint2 v0 = __ldg(hs + (size_t)s0 * 16 + l);
        uint2 v1 = __ldg(hs + (size_t)s1 * 16 + l);
        uint2 v2 = __ldg(hs + (size_t)s2 * 16 + l);
        uint2 v3 = __ldg(hs + (size_t)s3 * 16 + l);
        float2 a0 = u2f(v0.x), a1 = u2f(v0.y);
        float2 b0 = u2f(v1.x), b1v = u2f(v1.y);
        float2 c0 = u2f(v2.x), c1 = u2f(v2.y);
        float2 d0 = u2f(v3.x), d1 = u2f(v3.y);
        acc.x += (a0.x + b0.x) + (c0.x + d0.x);
        acc.y += (a0.y + b0.y) + (c0.y + d0.y);
        acc.z += (a1.x + b1v.x) + (c1.x + d1.x);
        acc.w += (a1.y + b1v.y) + (c1.y + d1.y);
    }
    for (; i < end; i++) {
        int s = __ldg(g_adj + i);
        uint2 v = __ldg(hs + (size_t)s * 16 + l);
        float2 a0 = u2f(v.x), a1 = u2f(v.y);
        acc.x += a0.x; acc.y += a0.y; acc.z += a1.x; acc.w += a1.y;
    }
    float di = __ldg(&g_dinv[gh]);
    float4 b = __ldg((const float4*)b2 + l);
    ((float4*)out)[(size_t)gh * 16 + l] =
        make_float4(fmaf(di, acc.x, b.x), fmaf(di, acc.y, b.y),
                    fmaf(di, acc.z, b.z), fmaf(di, acc.w, b.w));
}

// ---------------- launch ----------------
extern "C" void kernel_launch(void* const* d_in, const int* in_sizes, int n_in,
                              void* d_out, int out_size) {
    const int*   edge = (const int*)d_in[0];     // [2, E]: src row, dst row
    const float* x    = (const float*)d_in[1];   // [N, 128]
    const float* W1   = (const float*)d_in[2];   // [128, 128]
    const float* b1   = (const float*)d_in[3];   // [128]
    const float* W2   = (const float*)d_in[4];   // [128, 64]
    const float* b2   = (const float*)d_in[5];   // [64]
    float* out = (float*)d_out;                  // [N, 64]

    const int* src = edge;
    const int* dst = edge + N_EDGES;

    // CSR build (+ degree/dinv)
    k_zero<<<SCAN_BLOCKS, 256>>>();
    k_hist<<<2048, 256>>>(dst);
    k_breduce<<<SCAN_BLOCKS, 256>>>();
    k_scanb<<<1, 512>>>();
    k_scanfinal<<<SCAN_BLOCKS, 256>>>();
    k_fill<<<2048, 256>>>(src, dst);

    // layer 1
    k_gemm1<<<(N_NODES + 127) / 128, 256>>>(x, W1);
    k_agg1<<<(N_NODES * 32 + 255) / 256, 256>>>(b1);

    // layer 2
    k_gemm2<<<(N_NODES + 255) / 256, 256>>>(W2);
    k_agg2<<<(N_NODES * 16 + 255) / 256, 256>>>(b2, out);
}

// round 7
// speedup vs baseline: 2.6246x; 1.7890x over previous
#include <cuda_runtime.h>
#include <cuda_fp16.h>
#include <mma.h>
#include <cstdint>

using namespace nvcuda;

// GCN: out = GCNConv2( relu(GCNConv1(x)) )
// Hs = dinv ⊙ (X W) via fp16 tensor cores (fp32 accum), messages stored fp16;
// agg[d] = Hs[d] + sum_{s->d} Hs[s] (CSR gather, fp32 accum);
// layer1: x1 = relu(dinv*agg + b1) stored fp16;  layer2: out = dinv*agg + b2 (fp32)

#define N_NODES 100000
#define N_EDGES 1600000
#define EMB 128
#define HID 128
#define RPR 64
#define SCAN_BLOCKS 391   // ceil(100000/256)

// ---------------- scratch (device globals, allocation-free) ----------------
__device__ float  g_dinv[N_NODES];
__device__ __half g_Hs [(long long)N_NODES * HID];   // layer1 scaled hidden (fp16)
__device__ __half g_X1h[(long long)N_NODES * HID];   // relu(conv1) output (fp16)
__device__ __half g_Hs2[(long long)N_NODES * RPR];   // layer2 scaled hidden (fp16)
__device__ int    g_cnt[N_NODES];
__device__ int    g_rowptr[N_NODES + 1];
__device__ int    g_cur[N_NODES];
__device__ int    g_blocksum[SCAN_BLOCKS];
__device__ int    g_adj[N_EDGES];

// ---------------- helpers ----------------
__device__ __forceinline__ unsigned int h2u(float a, float b) {
    __half2 h = __floats2half2_rn(a, b);
    return *reinterpret_cast<unsigned int*>(&h);
}
__device__ __forceinline__ float2 u2f(unsigned int u) {
    __half2 h = *reinterpret_cast<__half2*>(&u);
    return __half22float2(h);
}

// ---------------- CSR build + degree ----------------
__global__ void k_zero() {
    int i = blockIdx.x * blockDim.x + threadIdx.x;
    if (i < N_NODES) g_cnt[i] = 0;
}

__global__ void k_hist(const int* __restrict__ dst) {
    int stride = gridDim.x * blockDim.x;
    for (int e = blockIdx.x * blockDim.x + threadIdx.x; e < N_EDGES; e += stride)
        atomicAdd(&g_cnt[dst[e]], 1);
}

__global__ void k_breduce() {
    __shared__ int sh[256];
    int i = blockIdx.x * 256 + threadIdx.x;
    int v = (i < N_NODES) ? g_cnt[i] : 0;
    sh[threadIdx.x] = v;
    __syncthreads();
    for (int s = 128; s > 0; s >>= 1) {
        if (threadIdx.x < s) sh[threadIdx.x] += sh[threadIdx.x + s];
        __syncthreads();
    }
    if (threadIdx.x == 0) g_blocksum[blockIdx.x] = sh[0];
}

__global__ void k_scanb() {   // single block of 512, exclusive scan of block sums
    __shared__ int sh[512];
    int t = threadIdx.x;
    int v = (t < SCAN_BLOCKS) ? g_blocksum[t] : 0;
    sh[t] = v;
    __syncthreads();
    for (int off = 1; off < 512; off <<= 1) {
        int add = 0;
        if (t >= off) add = sh[t - off];
        __syncthreads();
        sh[t] += add;
        __syncthreads();
    }
    if (t < SCAN_BLOCKS) g_blocksum[t] = sh[t] - v;   // exclusive
}

__global__ void k_scanfinal() {
    __shared__ int sh[256];
    int t = threadIdx.x;
    int i = blockIdx.x * 256 + t;
    int v = (i < N_NODES) ? g_cnt[i] : 0;
    sh[t] = v;
    __syncthreads();
    for (int off = 1; off < 256; off <<= 1) {
        int add = 0;
        if (t >= off) add = sh[t - off];
        __syncthreads();
        sh[t] += add;
        __syncthreads();
    }
    int excl = sh[t] - v + g_blocksum[blockIdx.x];
    if (i < N_NODES) {
        g_rowptr[i] = excl;
        g_cur[i]    = excl;
        g_dinv[i]   = rsqrtf(1.0f + (float)v);   // +1 for self loop
    }
    if (i == N_NODES - 1) g_rowptr[N_NODES] = excl + v;
}

__global__ void k_fill(const int* __restrict__ src, const int* __restrict__ dst) {
    int stride = gridDim.x * blockDim.x;
    for (int e = blockIdx.x * blockDim.x + threadIdx.x; e < N_EDGES; e += stride) {
        int d = dst[e];
        int pos = atomicAdd(&g_cur[d], 1);
        g_adj[pos] = src[e];
    }
}

// ---------------- layer-1 GEMM (tensor cores): Hs = dinv * (x @ W1), fp16 out ---
// block 256 thr = 8 warps; tile 128 rows x 128 cols; K=128 fully in smem.
// A (x tile) fp32->fp16 on smem fill; B = W1 fp16 in smem; C staged in smem fp32.
#define LDA1 136
#define LDC1 132
__global__ __launch_bounds__(256)
void k_gemm1_tc(const float* __restrict__ x, const float* __restrict__ W1) {
    extern __shared__ char dynsmem[];
    __half* A_h = (__half*)dynsmem;                 // [128][136]
    __half* B_h = A_h + 128 * LDA1;                 // [128][136]
    float*  C_f = (float*)dynsmem;                  // [128][132] (reuse after mma)

    const int tid  = threadIdx.x;
    const int warp = tid >> 5;
    const int rowBase = blockIdx.x * 128;

    // fill B: W1 fp32 -> fp16 (128x128), pairs
    for (int idx = tid; idx < 128 * 64; idx += 256) {
        int k = idx >> 6, n2 = idx & 63;
        float2 w = *(const float2*)&W1[k * HID + n2 * 2];
        *(unsigned int*)&B_h[k * LDA1 + n2 * 2] = h2u(w.x, w.y);
    }
    // fill A: x tile fp32 -> fp16, zero-pad invalid rows
    for (int idx = tid; idx < 128 * 32; idx += 256) {
        int r = idx >> 5, q4 = idx & 31;            // q4: group of 4 cols
        int gr = rowBase + r;
        unsigned int p0 = 0, p1 = 0;
        if (gr < N_NODES) {
            float4 v = *(const float4*)&x[(size_t)gr * EMB + q4 * 4];
            p0 = h2u(v.x, v.y);
            p1 = h2u(v.z, v.w);
        }
        *(unsigned int*)&A_h[r * LDA1 + q4 * 4]     = p0;
        *(unsigned int*)&A_h[r * LDA1 + q4 * 4 + 2] = p1;
    }
    __syncthreads();

    wmma::fragment<wmma::accumulator, 16, 16, 16, float> acc[8];
#pragma unroll
    for (int n = 0; n < 8; n++) wmma::fill_fragment(acc[n], 0.0f);

#pragma unroll
    for (int k = 0; k < 8; k++) {
        wmma::fragment<wmma::matrix_a, 16, 16, 16, __half, wmma::row_major> a;
        wmma::load_matrix_sync(a, &A_h[warp * 16 * LDA1 + k * 16], LDA1);
#pragma unroll
        for (int n = 0; n < 8; n++) {
            wmma::fragment<wmma::matrix_b, 16, 16, 16, __half, wmma::row_major> b;
            wmma::load_matrix_sync(b, &B_h[k * 16 * LDA1 + n * 16], LDA1);
            wmma::mma_sync(acc[n], a, b, acc[n]);
        }
    }
    __syncthreads();   // done reading A/B smem; reuse as C staging

#pragma unroll
    for (int n = 0; n < 8; n++)
        wmma::store_matrix_sync(&C_f[warp * 16 * LDC1 + n * 16], acc[n], LDC1,
                                wmma::mem_row_major);
    __syncthreads();

    // epilogue: scale by dinv, convert fp16, write. 2 threads/row, 64 cols each.
    {
        int r = tid >> 1, seg = tid & 1;
        int gr = rowBase + r;
        if (gr < N_NODES) {
            float di = __ldg(&g_dinv[gr]);
            const float* cr = &C_f[r * LDC1 + seg * 64];
            __half* hp = g_Hs + (size_t)gr * HID + seg * 64;
#pragma unroll
            for (int q = 0; q < 8; q++) {
                float4 v0 = *(const float4*)(cr + q * 8);
                float4 v1 = *(const float4*)(cr + q * 8 + 4);
                uint4 o;
                o.x = h2u(v0.x * di, v0.y * di);
                o.y = h2u(v0.z * di, v0.w * di);
                o.z = h2u(v1.x * di, v1.y * di);
                o.w = h2u(v1.z * di, v1.w * di);
                *(uint4*)(hp + q * 8) = o;
            }
        }
    }
}

// ---------------- layer-1 aggregate + relu + bias -> x1 (fp16) ----------------
// warp per node; lane covers 4 consecutive cols (uint2 = 4 halfs)
__global__ void k_agg1(const float* __restrict__ b1) {
    int gw = (blockIdx.x * blockDim.x + threadIdx.x) >> 5;
    if (gw >= N_NODES) return;
    const int lane = threadIdx.x & 31;
    const uint2* hs = (const uint2*)g_Hs;     // row stride = 32 uint2

    uint2 sv = __ldg(hs + (size_t)gw * 32 + lane);   // self loop
    float2 f0 = u2f(sv.x), f1 = u2f(sv.y);
    float4 acc = make_float4(f0.x, f0.y, f1.x, f1.y);

    int beg = g_rowptr[gw], end = g_rowptr[gw + 1];
    int i = beg;
    for (; i + 4 <= end; i += 4) {
        int s0 = __ldg(g_adj + i),     s1 = __ldg(g_adj + i + 1);
        int s2 = __ldg(g_adj + i + 2), s3 = __ldg(g_adj + i + 3);
        uint2 v0 = __ldg(hs + (size_t)s0 * 32 + lane);
        uint2 v1 = __ldg(hs + (size_t)s1 * 32 + lane);
        uint2 v2 = __ldg(hs + (size_t)s2 * 32 + lane);
        uint2 v3 = __ldg(hs + (size_t)s3 * 32 + lane);
        float2 a0 = u2f(v0.x), a1 = u2f(v0.y);
        float2 b0 = u2f(v1.x), b1v = u2f(v1.y);
        float2 c0 = u2f(v2.x), c1 = u2f(v2.y);
        float2 d0 = u2f(v3.x), d1 = u2f(v3.y);
        acc.x += (a0.x + b0.x) + (c0.x + d0.x);
        acc.y += (a0.y + b0.y) + (c0.y + d0.y);
        acc.z += (a1.x + b1v.x) + (c1.x + d1.x);
        acc.w += (a1.y + b1v.y) + (c1.y + d1.y);
    }
    for (; i < end; i++) {
        int s = __ldg(g_adj + i);
        uint2 v = __ldg(hs + (size_t)s * 32 + lane);
        float2 a0 = u2f(v.x), a1 = u2f(v.y);
        acc.x += a0.x; acc.y += a0.y; acc.z += a1.x; acc.w += a1.y;
    }
    float di = __ldg(&g_dinv[gw]);
    float4 b = __ldg((const float4*)b1 + lane);
    float rx = fmaxf(fmaf(di, acc.x, b.x), 0.0f);
    float ry = fmaxf(fmaf(di, acc.y, b.y), 0.0f);
    float rz = fmaxf(fmaf(di, acc.z, b.z), 0.0f);
    float rw = fmaxf(fmaf(di, acc.w, b.w), 0.0f);
    uint2 o;
    o.x = h2u(rx, ry);
    o.y = h2u(rz, rw);
    ((uint2*)g_X1h)[(size_t)gw * 32 + lane] = o;
}

// ---------------- layer-2 GEMM (tensor cores): Hs2 = dinv * (x1 @ W2), fp16 out
// block 256 thr = 8 warps; tile 128 rows x 64 cols; K=128 in smem.
#define LDA2 136
#define LDB2 72
#define LDC2 68
__global__ __launch_bounds__(256)
void k_gemm2_tc(const float* __restrict__ W2) {
    extern __shared__ char dynsmem[];
    __half* A_h = (__half*)dynsmem;                 // [128][136]
    __half* B_h = A_h + 128 * LDA2;                 // [128][72]
    float*  C_f = (float*)dynsmem;                  // [128][68] (reuse)

    const int tid  = threadIdx.x;
    const int warp = tid >> 5;
    const int rowBase = blockIdx.x * 128;

    // fill B: W2 fp32 -> fp16 (128x64)
    for (int idx = tid; idx < 128 * 32; idx += 256) {
        int k = idx >> 5, n2 = idx & 31;
        float2 w = *(const float2*)&W2[k * RPR + n2 * 2];
        *(unsigned int*)&B_h[k * LDB2 + n2 * 2] = h2u(w.x, w.y);
    }
    // fill A: X1h fp16 direct copy (uint4 = 8 halfs)
    for (int idx = tid; idx < 128 * 16; idx += 256) {
        int r = idx >> 4, q = idx & 15;
        int gr = rowBase + r;
        uint4 v = make_uint4(0, 0, 0, 0);
        if (gr < N_NODES)
            v = *(const uint4*)&g_X1h[(size_t)gr * HID + q * 8];
        *(uint4*)&A_h[r * LDA2 + q * 8] = v;
    }
    __syncthreads();

    wmma::fragment<wmma::accumulator, 16, 16, 16, float> acc[4];
#pragma unroll
    for (int n = 0; n < 4; n++) wmma::fill_fragment(acc[n], 0.0f);

#pragma unroll
    for (int k = 0; k < 8; k++) {
        wmma::fragment<wmma::matrix_a, 16, 16, 16, __half, wmma::row_major> a;
        wmma::load_matrix_sync(a, &A_h[warp * 16 * LDA2 + k * 16], LDA2);
#pragma unroll
        for (int n = 0; n < 4; n++) {
            wmma::fragment<wmma::matrix_b, 16, 16, 16, __half, wmma::row_major> b;
            wmma::load_matrix_sync(b, &B_h[k * 16 * LDB2 + n * 16], LDB2);
            wmma::mma_sync(acc[n], a, b, acc[n]);
        }
    }
    __syncthreads();

#pragma unroll
    for (int n = 0; n < 4; n++)
        wmma::store_matrix_sync(&C_f[warp * 16 * LDC2 + n * 16], acc[n], LDC2,
                                wmma::mem_row_major);
    __syncthreads();

    // epilogue: 2 threads/row, 32 cols each
    {
        int r = tid >> 1, seg = tid & 1;
        int gr = rowBase + r;
        if (gr < N_NODES) {
            float di = __ldg(&g_dinv[gr]);
            const float* cr = &C_f[r * LDC2 + seg * 32];
            __half* hp = g_Hs2 + (size_t)gr * RPR + seg * 32;
#pragma unroll
            for (int q = 0; q < 4; q++) {
                float4 v0 = *(const float4*)(cr + q * 8);
                float4 v1 = *(const float4*)(cr + q * 8 + 4);
                uint4 o;
                o.x = h2u(v0.x * di, v0.y * di);
                o.y = h2u(v0.z * di, v0.w * di);
                o.z = h2u(v1.x * di, v1.y * di);
                o.w = h2u(v1.z * di, v1.w * di);
                *(uint4*)(hp + q * 8) = o;
            }
        }
    }
}

// ---------------- layer-2 aggregate + bias -> out ----------------
// half-warp (16 lanes x uint2 = 64 halfs) per node
__global__ void k_agg2(const float* __restrict__ b2, float* __restrict__ out) {
    int gh = (blockIdx.x * blockDim.x + threadIdx.x) >> 4;
    if (gh >= N_NODES) return;
    const int l = threadIdx.x & 15;
    const uint2* hs = (const uint2*)g_Hs2;    // row stride = 16 uint2

    uint2 sv = __ldg(hs + (size_t)gh * 16 + l);   // self loop
    float2 f0 = u2f(sv.x), f1 = u2f(sv.y);
    float4 acc = make_float4(f0.x, f0.y, f1.x, f1.y);

    int beg = g_rowptr[gh], end = g_rowptr[gh + 1];
    int i = beg;
    for (; i + 4 <= end; i += 4) {
        int s0 = __ldg(g_adj + i),     s1 = __ldg(g_adj + i + 1);
        int s2 = __ldg(g_adj + i + 2), s3 = __ldg(g_adj + i + 3);
        uint2 v0 = __ldg(hs + (size_t)s0 * 16 + l);
        uint2 v1 = __ldg(hs + (size_t)s1 * 16 + l);
        uint2 v2 = __ldg(hs + (size_t)s2 * 16 + l);
        uint2 v3 = __ldg(hs + (size_t)s3 * 16 + l);
        float2 a0 = u2f(v0.x), a1 = u2f(v0.y);
        float2 b0 = u2f(v1.x), b1v = u2f(v1.y);
        float2 c0 = u2f(v2.x), c1 = u2f(v2.y);
        float2 d0 = u2f(v3.x), d1 = u2f(v3.y);
        acc.x += (a0.x + b0.x) + (c0.x + d0.x);
        acc.y += (a0.y + b0.y) + (c0.y + d0.y);
        acc.z += (a1.x + b1v.x) + (c1.x + d1.x);
        acc.w += (a1.y + b1v.y) + (c1.y + d1.y);
    }
    for (; i < end; i++) {
        int s = __ldg(g_adj + i);
        uint2 v = __ldg(hs + (size_t)s * 16 + l);
        float2 a0 = u2f(v.x), a1 = u2f(v.y);
        acc.x += a0.x; acc.y += a0.y; acc.z += a1.x; acc.w += a1.y;
    }
    float di = __ldg(&g_dinv[gh]);
    float4 b = __ldg((const float4*)b2 + l);
    ((float4*)out)[(size_t)gh * 16 + l] =
        make_float4(fmaf(di, acc.x, b.x), fmaf(di, acc.y, b.y),
                    fmaf(di, acc.z, b.z), fmaf(di, acc.w, b.w));
}

// ---------------- launch ----------------
#define SMEM_GEMM1 (2 * 128 * LDA1 * 2)                 // 69632 B
#define SMEM_GEMM2 (128 * LDA2 * 2 + 128 * LDB2 * 2)    // 53248 B

extern "C" void kernel_launch(void* const* d_in, const int* in_sizes, int n_in,
                              void* d_out, int out_size) {
    const int*   edge = (const int*)d_in[0];     // [2, E]: src row, dst row
    const float* x    = (const float*)d_in[1];   // [N, 128]
    const float* W1   = (const float*)d_in[2];   // [128, 128]
    const float* b1   = (const float*)d_in[3];   // [128]
    const float* W2   = (const float*)d_in[4];   // [128, 64]
    const float* b2   = (const float*)d_in[5];   // [64]
    float* out = (float*)d_out;                  // [N, 64]

    const int* src = edge;
    const int* dst = edge + N_EDGES;

    cudaFuncSetAttribute(k_gemm1_tc, cudaFuncAttributeMaxDynamicSharedMemorySize,
                         SMEM_GEMM1);
    cudaFuncSetAttribute(k_gemm2_tc, cudaFuncAttributeMaxDynamicSharedMemorySize,
                         SMEM_GEMM2);

    // CSR build (+ degree/dinv)
    k_zero<<<SCAN_BLOCKS, 256>>>();
    k_hist<<<2048, 256>>>(dst);
    k_breduce<<<SCAN_BLOCKS, 256>>>();
    k_scanb<<<1, 512>>>();
    k_scanfinal<<<SCAN_BLOCKS, 256>>>();
    k_fill<<<2048, 256>>>(src, dst);

    // layer 1
    k_gemm1_tc<<<(N_NODES + 127) / 128, 256, SMEM_GEMM1>>>(x, W1);
    k_agg1<<<(N_NODES * 32 + 255) / 256, 256>>>(b1);

    // layer 2
    k_gemm2_tc<<<(N_NODES + 127) / 128, 256, SMEM_GEMM2>>>(W2);
    k_agg2<<<(N_NODES * 16 + 255) / 256, 256>>>(b2, out);
}